// round 13
// baseline (speedup 1.0000x reference)
#include <cuda_runtime.h>
#include <cuda_fp16.h>
#include <math.h>
#include <stdint.h>

// ---------------- problem constants ----------------
#define B_   32
#define CI   64
#define HH   128
#define WW   128
#define HW_  16384
#define OH   126
#define OW   126
#define CO   128
#define NT1  63
#define NCOMP 16

// ---------------- device scratch ----------------
__device__ __half g_U[NCOMP * CO * CI];          // 256 KB [c][co][ci]
__device__ float  g_partial[B_ * 126 * CO];      // [b][th*2+half][co]

// ---------------- smem layout (bytes) ----------------
#define V_STRIDE 80
#define V_CB     (64 * V_STRIDE)        // 5120 per comp
#define A_OFF    (16 * V_CB)            // 81920
#define A_CB     16384                  // per comp: 128 co x 128B (XOR-swizzled)
#define SMEM_DYN (A_OFF + 2 * A_CB)     // 114688 (112 KB) -> 2 CTAs/SM

// ---------------- helpers ----------------
__device__ __forceinline__ uint32_t smem_u32(const void* p) {
    uint32_t a;
    asm("{ .reg .u64 t; cvta.to.shared.u64 t, %1; cvt.u32.u64 %0, t; }" : "=r"(a) : "l"(p));
    return a;
}
__device__ __forceinline__ uint64_t to_global(const void* p) {
    uint64_t g;
    asm("cvta.to.global.u64 %0, %1;" : "=l"(g) : "l"(p));
    return g;
}
__device__ __forceinline__ float gelu_t(float v) {
    float u = 0.7978845608028654f * fmaf(0.044715f * v, v * v, v);
    float t;
    asm("tanh.approx.f32 %0, %1;" : "=f"(t) : "f"(u));
    return 0.5f * v * (1.0f + t);
}

#define CP16(dst, src) asm volatile("cp.async.ca.shared.global [%0], [%1], 16;" :: "r"(dst), "l"(src))
#define CP_COMMIT()    asm volatile("cp.async.commit_group;" ::: "memory")
#define CP_WAIT1()     asm volatile("cp.async.wait_group 1;" ::: "memory")
#define CP_WAIT0()     asm volatile("cp.async.wait_group 0;" ::: "memory")

#define LDSM_X4(r, a) \
    asm volatile("ldmatrix.sync.aligned.m8n8.x4.shared.b16 {%0,%1,%2,%3}, [%4];" \
        : "=r"((r)[0]), "=r"((r)[1]), "=r"((r)[2]), "=r"((r)[3]) : "r"(a))
#define LDSM_X2T(r, a) \
    asm volatile("ldmatrix.sync.aligned.m8n8.x2.trans.shared.b16 {%0,%1}, [%2];" \
        : "=r"((r)[0]), "=r"((r)[1]) : "r"(a))
#define MMA16816F(d, a, bb) \
    asm volatile("mma.sync.aligned.m16n8k16.row.col.f32.f16.f16.f32 " \
        "{%0,%1,%2,%3}, {%4,%5,%6,%7}, {%8,%9}, {%0,%1,%2,%3};" \
        : "+f"((d)[0]), "+f"((d)[1]), "+f"((d)[2]), "+f"((d)[3]) \
        : "r"((a)[0]), "r"((a)[1]), "r"((a)[2]), "r"((a)[3]), "r"((bb)[0]), "r"((bb)[1]))

// ---------------- U = G g G^T ----------------
__global__ void wu_kernel(const float* __restrict__ w)
{
    const int co = blockIdx.x;
    const int ci = threadIdx.x;
    const float* g = w + (co * CI + ci) * 9;
    float q[3][3];
#pragma unroll
    for (int r = 0; r < 3; ++r)
#pragma unroll
        for (int c = 0; c < 3; ++c) q[r][c] = g[r * 3 + c];
    float t[4][3];
#pragma unroll
    for (int c = 0; c < 3; ++c) {
        t[0][c] = q[0][c];
        t[1][c] = 0.5f * (q[0][c] + q[1][c] + q[2][c]);
        t[2][c] = 0.5f * (q[0][c] - q[1][c] + q[2][c]);
        t[3][c] = q[2][c];
    }
#pragma unroll
    for (int r = 0; r < 4; ++r) {
        float u0 = t[r][0];
        float u1 = 0.5f * (t[r][0] + t[r][1] + t[r][2]);
        float u2 = 0.5f * (t[r][0] - t[r][1] + t[r][2]);
        float u3 = t[r][2];
        g_U[((r * 4 + 0) * CO + co) * CI + ci] = __float2half(u0);
        g_U[((r * 4 + 1) * CO + co) * CI + ci] = __float2half(u1);
        g_U[((r * 4 + 2) * CO + co) * CI + ci] = __float2half(u2);
        g_U[((r * 4 + 3) * CO + co) * CI + ci] = __float2half(u3);
    }
}

// ---------------- fused: transform + GEMM + output transform + pool ----------------
__global__ void __launch_bounds__(256, 2)
wino_fused(const float* __restrict__ x, const float* __restrict__ bias)
{
    extern __shared__ char smem[];
    const uint32_t sb = smem_u32(smem);
    const int tid  = threadIdx.x;
    const int wid  = tid >> 5;
    const int lane = tid & 31;
    const int mg = wid & 1;        // co half
    const int ng = wid >> 1;       // 8-tile group (0..3)

    const int th   = blockIdx.x >> 1;    // 0..62
    const int half = blockIdx.x & 1;     // tile-row half
    const int b    = blockIdx.y;

    const uint64_t gU = to_global(g_U);

    // ---- A prefetch (single comp, swizzled) ----
    auto loadA = [&](int c, int buf) {
        const uint32_t aOff = sb + A_OFF + (uint32_t)buf * A_CB;
#pragma unroll
        for (int it = 0; it < 4; ++it) {
            int idx = tid + it * 256;        // 0..1023
            int co = idx >> 3, q = idx & 7;
            CP16(aOff + co * 128 + ((q ^ (co & 7)) << 4),
                 gU + ((uint64_t)c << 14) + co * 128 + q * 16);
        }
    };

    loadA(0, 0); CP_COMMIT();
    loadA(1, 1); CP_COMMIT();

    // ---- phase 1: direct-LDG input transform (no barriers) ----
    const int ci_l = tid >> 4;     // 0..15
    const int tp   = tid & 15;     // tile pair within this half
    const int twg  = half * 32 + tp * 2;            // global tile index
    const bool v1  = (twg + 1) < NT1;

    const float* xb = x + (size_t)b * CI * HW_ + (size_t)th * 2 * WW
                        + half * 64 + 4 * tp;
    const float* xlast = x + (size_t)B_ * CI * HW_ - 2;

#pragma unroll
    for (int g = 0; g < 4; ++g) {
        const int ci = g * 16 + ci_l;
        const float* base = xb + (size_t)ci * HW_;
        float dd[4][6];
#pragma unroll
        for (int r = 0; r < 4; ++r) {
            const float* row = base + r * WW;
            float2 a0 = *(const float2*)(row);
            float2 a1 = *(const float2*)(row + 2);
            const float* p2 = row + 4;
            if (p2 > xlast) p2 = xlast;      // only feeds masked V1
            float2 a2 = *(const float2*)(p2);
            dd[r][0] = a0.x; dd[r][1] = a0.y; dd[r][2] = a1.x;
            dd[r][3] = a1.y; dd[r][4] = a2.x; dd[r][5] = a2.y;
        }
        float V0[16], V1[16];
#pragma unroll
        for (int tile = 0; tile < 2; ++tile) {
            const int o = tile * 2;
            float E[4][4];
#pragma unroll
            for (int r = 0; r < 4; ++r) {
                E[r][0] = dd[r][o + 0] - dd[r][o + 2];
                E[r][1] = dd[r][o + 1] + dd[r][o + 2];
                E[r][2] = dd[r][o + 2] - dd[r][o + 1];
                E[r][3] = dd[r][o + 1] - dd[r][o + 3];
            }
            float* V = tile ? V1 : V0;
#pragma unroll
            for (int j = 0; j < 4; ++j) {
                V[0 * 4 + j] = E[0][j] - E[2][j];
                V[1 * 4 + j] = E[1][j] + E[2][j];
                V[2 * 4 + j] = E[2][j] - E[1][j];
                V[3 * 4 + j] = E[1][j] - E[3][j];
            }
        }
        char* vdst = smem + ci * V_STRIDE + tp * 4;
#pragma unroll
        for (int c = 0; c < 16; ++c) {
            __half2 pk = __floats2half2_rn(V0[c], v1 ? V1[c] : 0.0f);
            *(uint32_t*)(vdst + c * V_CB) = reinterpret_cast<uint32_t&>(pk);
        }
    }

    // ---- phase 2: 16 comps, resident B, A double-buffered ----
    float y[4][4][4];
#pragma unroll
    for (int a = 0; a < 4; ++a)
#pragma unroll
        for (int e = 0; e < 4; ++e)
#pragma unroll
            for (int q = 0; q < 4; ++q) y[a][e][q] = 0.0f;

    const int laneRow = mg * 64 + (lane & 15);
    const int lane7   = lane & 7;
    const int laneChk = lane >> 4;
    const uint32_t bBase = sb + (lane & 15) * V_STRIDE + ng * 16;

#pragma unroll
    for (int c = 0; c < NCOMP; ++c) {
        if (c < NCOMP - 1) { CP_WAIT1(); } else { CP_WAIT0(); }
        __syncthreads();

        const uint32_t aOff = sb + A_OFF + (uint32_t)(c & 1) * A_CB;
        const uint32_t curB = (uint32_t)c * V_CB;

        float m[4][4];
#pragma unroll
        for (int mf = 0; mf < 4; ++mf)
#pragma unroll
            for (int e = 0; e < 4; ++e) m[mf][e] = 0.0f;

#pragma unroll
        for (int s4 = 0; s4 < 4; ++s4) {
            uint32_t afr[4][4], bfr[2];
            const int chunk = laneChk + s4 * 2;
            const uint32_t sw = (uint32_t)((chunk ^ lane7) << 4);
#pragma unroll
            for (int mf = 0; mf < 4; ++mf)
                LDSM_X4(afr[mf], aOff + (laneRow + mf * 16) * 128 + sw);
            LDSM_X2T(bfr, bBase + curB + s4 * 16 * V_STRIDE);
#pragma unroll
            for (int mf = 0; mf < 4; ++mf)
                MMA16816F(m[mf], afr[mf], bfr);
        }

        // fold (compile-time c after unroll: coefficients fold to 0/±1)
        const int cr = c >> 2, cc = c & 3;
        const float a0r = (cr < 3) ? 1.0f : 0.0f;
        const float a1r = (cr == 0) ? 0.0f : ((cr == 1) ? 1.0f : -1.0f);
        const float a0c = (cc < 3) ? 1.0f : 0.0f;
        const float a1c = (cc == 0) ? 0.0f : ((cc == 1) ? 1.0f : -1.0f);
        const float cq0 = a0r * a0c, cq1 = a0r * a1c;
        const float cq2 = a1r * a0c, cq3 = a1r * a1c;
#pragma unroll
        for (int mf = 0; mf < 4; ++mf)
#pragma unroll
            for (int e = 0; e < 4; ++e) {
                const float v = m[mf][e];
                y[mf][e][0] = fmaf(cq0, v, y[mf][e][0]);
                y[mf][e][1] = fmaf(cq1, v, y[mf][e][1]);
                y[mf][e][2] = fmaf(cq2, v, y[mf][e][2]);
                y[mf][e][3] = fmaf(cq3, v, y[mf][e][3]);
            }

        __syncthreads();
        if (c + 2 < NCOMP) { loadA(c + 2, c & 1); CP_COMMIT(); }
    }

    // ---- epilogue: bias + gelu + pool ----
    float* red = (float*)smem;     // aliases V (dead)
#pragma unroll
    for (int mf = 0; mf < 4; ++mf) {
#pragma unroll
        for (int hh = 0; hh < 2; ++hh) {
            const int co = mg * 64 + mf * 16 + hh * 8 + (lane >> 2);
            const float bv = __ldg(bias + co);
            float s = 0.0f;
#pragma unroll
            for (int e = 0; e < 2; ++e) {
                const int tw = half * 32 + ng * 8 + (lane & 3) * 2 + e;
                if (tw < NT1) {
#pragma unroll
                    for (int q = 0; q < 4; ++q)
                        s += gelu_t(y[mf][hh * 2 + e][q] + bv);
                }
            }
            s += __shfl_xor_sync(0xFFFFFFFFu, s, 1);
            s += __shfl_xor_sync(0xFFFFFFFFu, s, 2);
            if ((lane & 3) == 0) red[ng * CO + co] = s;
        }
    }
    __syncthreads();
    if (tid < CO) {
        float t = red[tid] + red[CO + tid] + red[2 * CO + tid] + red[3 * CO + tid];
        g_partial[((size_t)b * 126 + blockIdx.x) * CO + tid] = t;
    }
}

// ---------------- final reduction ----------------
__global__ void reduce_kernel(float* __restrict__ out)
{
    __shared__ float sred[512];
    const int b   = blockIdx.x;
    const int co  = threadIdx.x & 127;
    const int seg = threadIdx.x >> 7;
    const int r0 = seg * 32;
    const int r1 = (r0 + 32 < 126) ? (r0 + 32) : 126;
    float s = 0.0f;
    for (int r = r0; r < r1; ++r)
        s += g_partial[((size_t)b * 126 + r) * CO + co];
    sred[threadIdx.x] = s;
    __syncthreads();
    if (threadIdx.x < 128) {
        float r = sred[threadIdx.x] + sred[threadIdx.x + 128]
                + sred[threadIdx.x + 256] + sred[threadIdx.x + 384];
        out[b * CO + threadIdx.x] = r * (1.0f / (float)(OH * OW));
    }
}

extern "C" void kernel_launch(void* const* d_in, const int* in_sizes, int n_in,
                              void* d_out, int out_size)
{
    const float* x      = (const float*)d_in[0];
    const float* weight = (const float*)d_in[1];
    const float* bias   = (const float*)d_in[2];
    float* out = (float*)d_out;

    cudaFuncSetAttribute(wino_fused,
                         cudaFuncAttributeMaxDynamicSharedMemorySize, SMEM_DYN);

    wu_kernel<<<CO, CI>>>(weight);
    wino_fused<<<dim3(126, B_), 256, SMEM_DYN>>>(x, bias);
    reduce_kernel<<<B_, 512>>>(out);
}

// round 14
// speedup vs baseline: 1.5872x; 1.5872x over previous
#include <cuda_runtime.h>
#include <cuda_fp16.h>
#include <math.h>
#include <stdint.h>

// ---------------- problem constants ----------------
#define B_   32
#define CI   64
#define HH   128
#define WW   128
#define HW_  16384
#define OH   126
#define OW   126
#define CO   128
#define NT1  63
#define NCOMP 16

// ---------------- device scratch ----------------
__device__ __half g_U[NCOMP * CO * CI];     // 256 KB [c][co][ci]
__device__ float  g_partial[B_ * NT1 * CO]; // [b][th][co]

// ---------------- smem layout (bytes) ----------------
#define V_CB     9216                   // per comp: 64 ci x 144B
#define A_OFF    (16 * V_CB)            // 147456
#define A_CB     18432                  // per comp: 128 co x 144B
#define A_STG    (2 * A_CB)             // 36864 per stage (2 comps)
#define SMEM_DYN (A_OFF + 2 * A_STG)    // 221184

// ---------------- helpers ----------------
__device__ __forceinline__ uint32_t smem_u32(const void* p) {
    uint32_t a;
    asm("{ .reg .u64 t; cvta.to.shared.u64 t, %1; cvt.u32.u64 %0, t; }" : "=r"(a) : "l"(p));
    return a;
}
__device__ __forceinline__ uint64_t to_global(const void* p) {
    uint64_t g;
    asm("cvta.to.global.u64 %0, %1;" : "=l"(g) : "l"(p));
    return g;
}
__device__ __forceinline__ float gelu_t(float v) {
    float u = 0.7978845608028654f * fmaf(0.044715f * v, v * v, v);
    float t;
    asm("tanh.approx.f32 %0, %1;" : "=f"(t) : "f"(u));
    return 0.5f * v * (1.0f + t);
}

#define CP16(dst, src) asm volatile("cp.async.ca.shared.global [%0], [%1], 16;" :: "r"(dst), "l"(src))
#define CP_COMMIT()    asm volatile("cp.async.commit_group;" ::: "memory")
#define CP_WAIT1()     asm volatile("cp.async.wait_group 1;" ::: "memory")
#define CP_WAIT0()     asm volatile("cp.async.wait_group 0;" ::: "memory")

#define LDSM_X4(r, a) \
    asm volatile("ldmatrix.sync.aligned.m8n8.x4.shared.b16 {%0,%1,%2,%3}, [%4];" \
        : "=r"((r)[0]), "=r"((r)[1]), "=r"((r)[2]), "=r"((r)[3]) : "r"(a))
#define LDSM_X2T(r, a) \
    asm volatile("ldmatrix.sync.aligned.m8n8.x2.trans.shared.b16 {%0,%1}, [%2];" \
        : "=r"((r)[0]), "=r"((r)[1]) : "r"(a))
#define MMA16816F(d, a, bb) \
    asm volatile("mma.sync.aligned.m16n8k16.row.col.f32.f16.f16.f32 " \
        "{%0,%1,%2,%3}, {%4,%5,%6,%7}, {%8,%9}, {%0,%1,%2,%3};" \
        : "+f"((d)[0]), "+f"((d)[1]), "+f"((d)[2]), "+f"((d)[3]) \
        : "r"((a)[0]), "r"((a)[1]), "r"((a)[2]), "r"((a)[3]), "r"((bb)[0]), "r"((bb)[1]))

// ---------------- U = G g G^T ----------------
__global__ void wu_kernel(const float* __restrict__ w)
{
    const int co = blockIdx.x;
    const int ci = threadIdx.x;
    const float* g = w + (co * CI + ci) * 9;
    float q[3][3];
#pragma unroll
    for (int r = 0; r < 3; ++r)
#pragma unroll
        for (int c = 0; c < 3; ++c) q[r][c] = g[r * 3 + c];
    float t[4][3];
#pragma unroll
    for (int c = 0; c < 3; ++c) {
        t[0][c] = q[0][c];
        t[1][c] = 0.5f * (q[0][c] + q[1][c] + q[2][c]);
        t[2][c] = 0.5f * (q[0][c] - q[1][c] + q[2][c]);
        t[3][c] = q[2][c];
    }
#pragma unroll
    for (int r = 0; r < 4; ++r) {
        float u0 = t[r][0];
        float u1 = 0.5f * (t[r][0] + t[r][1] + t[r][2]);
        float u2 = 0.5f * (t[r][0] - t[r][1] + t[r][2]);
        float u3 = t[r][2];
        g_U[((r * 4 + 0) * CO + co) * CI + ci] = __float2half(u0);
        g_U[((r * 4 + 1) * CO + co) * CI + ci] = __float2half(u1);
        g_U[((r * 4 + 2) * CO + co) * CI + ci] = __float2half(u2);
        g_U[((r * 4 + 3) * CO + co) * CI + ci] = __float2half(u3);
    }
}

// ---------------- fused: transform + GEMM + output transform + pool ----------------
__global__ void __launch_bounds__(512, 1)
wino_fused(const float* __restrict__ x, const float* __restrict__ bias)
{
    extern __shared__ char smem[];
    const uint32_t sb = smem_u32(smem);
    const int tid  = threadIdx.x;
    const int wid  = tid >> 5;
    const int lane = tid & 31;
    const int mg = wid & 3;        // co quarter (32 rows)
    const int ng = wid >> 2;       // 16-tile group (0..3)

    const int th = blockIdx.x;     // 0..62
    const int b  = blockIdx.y;

    const uint64_t gU = to_global(g_U);

    // ---- A-stage prefetch (issued BEFORE phase 1 so U streams in under it) ----
    auto loadA_stage = [&](int s, int buf) {
        const uint32_t aOff = sb + A_OFF + (uint32_t)buf * A_STG;
#pragma unroll
        for (int k = 0; k < 2; ++k) {
            const int c = 2 * s + k;
#pragma unroll
            for (int it = 0; it < 2; ++it) {
                int idx = tid + it * 512;       // 0..1023
                int co = idx >> 3, q = idx & 7;
                CP16(aOff + k * A_CB + co * 144 + q * 16,
                     gU + ((uint64_t)c << 14) + co * 128 + q * 16);
            }
        }
    };

    loadA_stage(0, 0); CP_COMMIT();
    loadA_stage(1, 1); CP_COMMIT();

    // ---- phase 1: direct-LDG input transform, no staging, no barriers ----
    const int ci_l = tid >> 5;     // 0..15
    const int tp   = tid & 31;     // tile pair
    const int tw0  = tp * 2;
    const bool v1  = (tw0 + 1) < NT1;

    const float* xb = x + (size_t)b * CI * HW_ + (size_t)th * 2 * WW + 4 * tp;
    const float* xlast = x + (size_t)B_ * CI * HW_ - 2;   // clamp for tail overread

#pragma unroll
    for (int g = 0; g < 4; ++g) {
        const int ci = g * 16 + ci_l;
        const float* base = xb + (size_t)ci * HW_;
        float dd[4][6];
#pragma unroll
        for (int r = 0; r < 4; ++r) {
            const float* row = base + r * WW;
            float2 a0 = *(const float2*)(row);
            float2 a1 = *(const float2*)(row + 2);
            const float* p2 = row + 4;
            if (p2 > xlast) p2 = xlast;         // only feeds masked V1
            float2 a2 = *(const float2*)(p2);
            dd[r][0] = a0.x; dd[r][1] = a0.y; dd[r][2] = a1.x;
            dd[r][3] = a1.y; dd[r][4] = a2.x; dd[r][5] = a2.y;
        }
        float V0[16], V1[16];
#pragma unroll
        for (int tile = 0; tile < 2; ++tile) {
            const int o = tile * 2;
            float E[4][4];
#pragma unroll
            for (int r = 0; r < 4; ++r) {
                E[r][0] = dd[r][o + 0] - dd[r][o + 2];
                E[r][1] = dd[r][o + 1] + dd[r][o + 2];
                E[r][2] = dd[r][o + 2] - dd[r][o + 1];
                E[r][3] = dd[r][o + 1] - dd[r][o + 3];
            }
            float* V = tile ? V1 : V0;
#pragma unroll
            for (int j = 0; j < 4; ++j) {
                V[0 * 4 + j] = E[0][j] - E[2][j];
                V[1 * 4 + j] = E[1][j] + E[2][j];
                V[2 * 4 + j] = E[2][j] - E[1][j];
                V[3 * 4 + j] = E[1][j] - E[3][j];
            }
        }
        char* vdst = smem + ci * 144 + tp * 4;
#pragma unroll
        for (int c = 0; c < 16; ++c) {
            __half2 pk = __floats2half2_rn(V0[c], v1 ? V1[c] : 0.0f);
            *(uint32_t*)(vdst + c * V_CB) = reinterpret_cast<uint32_t&>(pk);
        }
    }
    // V visibility handled by the stage-0 __syncthreads below.

    // ---- phase 2: 8 stages x 2 comps; warp tile = 32 co x 16 tiles (mf2 x nb2) ----
    float y[2][2][4][4];   // [mf][nf][e][q]
#pragma unroll
    for (int a = 0; a < 2; ++a)
#pragma unroll
        for (int n = 0; n < 2; ++n)
#pragma unroll
            for (int e = 0; e < 4; ++e)
#pragma unroll
                for (int q = 0; q < 4; ++q) y[a][n][e][q] = 0.0f;

    const uint32_t aBase = sb + A_OFF + (mg * 32 + (lane & 15)) * 144 + (lane >> 4) * 16;
    const uint32_t bBase = sb + (lane & 15) * 144 + ng * 32;

#pragma unroll 1
    for (int s = 0; s < 8; ++s) {
        if (s < 7) { CP_WAIT1(); } else { CP_WAIT0(); }
        __syncthreads();
        const uint32_t stA = (uint32_t)(s & 1) * A_STG;

#pragma unroll
        for (int k = 0; k < 2; ++k) {
            const int c = 2 * s + k;
            const uint32_t curA = stA + (uint32_t)k * A_CB;
            const uint32_t curB = (uint32_t)c * V_CB;

            float m[2][2][4];
#pragma unroll
            for (int mf = 0; mf < 2; ++mf)
#pragma unroll
                for (int nf = 0; nf < 2; ++nf)
#pragma unroll
                    for (int e = 0; e < 4; ++e) m[mf][nf][e] = 0.0f;

#pragma unroll
            for (int s4 = 0; s4 < 4; ++s4) {
                uint32_t afr[2][4], bfr[2][2];
#pragma unroll
                for (int mf = 0; mf < 2; ++mf)
                    LDSM_X4(afr[mf], aBase + curA + mf * 16 * 144 + s4 * 32);
#pragma unroll
                for (int nf = 0; nf < 2; ++nf)
                    LDSM_X2T(bfr[nf], bBase + curB + s4 * 16 * 144 + nf * 16);
#pragma unroll
                for (int mf = 0; mf < 2; ++mf)
#pragma unroll
                    for (int nf = 0; nf < 2; ++nf)
                        MMA16816F(m[mf][nf], afr[mf], bfr[nf]);
            }

            // fold (AT0={1,1,1,0}, AT1={0,1,-1,-1})
            const int cr = c >> 2, cc = c & 3;
            const float a0r = (cr < 3) ? 1.0f : 0.0f;
            const float a1r = (cr == 0) ? 0.0f : ((cr == 1) ? 1.0f : -1.0f);
            const float a0c = (cc < 3) ? 1.0f : 0.0f;
            const float a1c = (cc == 0) ? 0.0f : ((cc == 1) ? 1.0f : -1.0f);
            const float cq0 = a0r * a0c, cq1 = a0r * a1c;
            const float cq2 = a1r * a0c, cq3 = a1r * a1c;
#pragma unroll
            for (int mf = 0; mf < 2; ++mf)
#pragma unroll
                for (int nf = 0; nf < 2; ++nf)
#pragma unroll
                    for (int e = 0; e < 4; ++e) {
                        const float v = m[mf][nf][e];
                        y[mf][nf][e][0] = fmaf(cq0, v, y[mf][nf][e][0]);
                        y[mf][nf][e][1] = fmaf(cq1, v, y[mf][nf][e][1]);
                        y[mf][nf][e][2] = fmaf(cq2, v, y[mf][nf][e][2]);
                        y[mf][nf][e][3] = fmaf(cq3, v, y[mf][nf][e][3]);
                    }
        }
        __syncthreads();
        if (s + 2 < 8) { loadA_stage(s + 2, s & 1); CP_COMMIT(); }
    }

    // ---- epilogue: bias + gelu + pool ----
    float* red = (float*)smem;     // aliases V (dead)
#pragma unroll
    for (int mf = 0; mf < 2; ++mf) {
#pragma unroll
        for (int hh = 0; hh < 2; ++hh) {
            const int co = mg * 32 + mf * 16 + hh * 8 + (lane >> 2);
            const float bv = __ldg(bias + co);
            float s = 0.0f;
#pragma unroll
            for (int nf = 0; nf < 2; ++nf) {
#pragma unroll
                for (int e = 0; e < 2; ++e) {
                    const int tw = ng * 16 + nf * 8 + (lane & 3) * 2 + e;
                    if (tw < NT1) {
#pragma unroll
                        for (int q = 0; q < 4; ++q)
                            s += gelu_t(y[mf][nf][hh * 2 + e][q] + bv);
                    }
                }
            }
            s += __shfl_xor_sync(0xFFFFFFFFu, s, 1);
            s += __shfl_xor_sync(0xFFFFFFFFu, s, 2);
            if ((lane & 3) == 0) red[ng * CO + co] = s;
        }
    }
    __syncthreads();
    if (tid < CO) {
        float t = red[tid] + red[CO + tid] + red[2 * CO + tid] + red[3 * CO + tid];
        g_partial[(b * NT1 + th) * CO + tid] = t;
    }
}

// ---------------- final reduction ----------------
__global__ void reduce_kernel(float* __restrict__ out)
{
    __shared__ float sred[512];
    const int b   = blockIdx.x;
    const int co  = threadIdx.x & 127;
    const int seg = threadIdx.x >> 7;
    const int r0 = seg * 16;
    const int r1 = (seg == 3) ? NT1 : (r0 + 16);
    float s = 0.0f;
    for (int r = r0; r < r1; ++r)
        s += g_partial[(b * NT1 + r) * CO + co];
    sred[threadIdx.x] = s;
    __syncthreads();
    if (threadIdx.x < 128) {
        float r = sred[threadIdx.x] + sred[threadIdx.x + 128]
                + sred[threadIdx.x + 256] + sred[threadIdx.x + 384];
        out[b * CO + threadIdx.x] = r * (1.0f / (float)(OH * OW));
    }
}

extern "C" void kernel_launch(void* const* d_in, const int* in_sizes, int n_in,
                              void* d_out, int out_size)
{
    const float* x      = (const float*)d_in[0];
    const float* weight = (const float*)d_in[1];
    const float* bias   = (const float*)d_in[2];
    float* out = (float*)d_out;

    cudaFuncSetAttribute(wino_fused,
                         cudaFuncAttributeMaxDynamicSharedMemorySize, SMEM_DYN);

    wu_kernel<<<CO, CI>>>(weight);
    wino_fused<<<dim3(NT1, B_), 512, SMEM_DYN>>>(x, bias);
    reduce_kernel<<<B_, 512>>>(out);
}

// round 15
// speedup vs baseline: 1.7176x; 1.0822x over previous
#include <cuda_runtime.h>
#include <cuda_fp16.h>
#include <math.h>
#include <stdint.h>

// ---------------- problem constants ----------------
#define B_   32
#define CI   64
#define HH   128
#define WW   128
#define HW_  16384
#define OH   126
#define OW   126
#define CO   128
#define NT1  63
#define NCOMP 16

// ---------------- device scratch ----------------
__device__ __half g_U[NCOMP * CO * CI];     // 256 KB [c][co][ci]
__device__ float  g_partial[B_ * NT1 * CO]; // [b][th][co]

// ---------------- smem layout (bytes) ----------------
#define V_CB     9216                   // per comp: 64 ci x 144B
#define A_OFF    (16 * V_CB)            // 147456
#define A_CB     18432                  // per comp: 128 co x 144B
#define A_STG    (2 * A_CB)             // 36864 per stage (2 comps)
#define SMEM_DYN (A_OFF + 2 * A_STG)    // 221184

// ---------------- helpers ----------------
__device__ __forceinline__ uint32_t smem_u32(const void* p) {
    uint32_t a;
    asm("{ .reg .u64 t; cvta.to.shared.u64 t, %1; cvt.u32.u64 %0, t; }" : "=r"(a) : "l"(p));
    return a;
}
__device__ __forceinline__ uint64_t to_global(const void* p) {
    uint64_t g;
    asm("cvta.to.global.u64 %0, %1;" : "=l"(g) : "l"(p));
    return g;
}
__device__ __forceinline__ float gelu_t(float v) {
    float u = 0.7978845608028654f * fmaf(0.044715f * v, v * v, v);
    float t;
    asm("tanh.approx.f32 %0, %1;" : "=f"(t) : "f"(u));
    return 0.5f * v * (1.0f + t);
}

#define CP16(dst, src) asm volatile("cp.async.ca.shared.global [%0], [%1], 16;" :: "r"(dst), "l"(src))
#define CP_COMMIT()    asm volatile("cp.async.commit_group;" ::: "memory")
#define CP_WAIT1()     asm volatile("cp.async.wait_group 1;" ::: "memory")
#define CP_WAIT0()     asm volatile("cp.async.wait_group 0;" ::: "memory")

#define LDSM_X4(r, a) \
    asm volatile("ldmatrix.sync.aligned.m8n8.x4.shared.b16 {%0,%1,%2,%3}, [%4];" \
        : "=r"((r)[0]), "=r"((r)[1]), "=r"((r)[2]), "=r"((r)[3]) : "r"(a))
#define LDSM_X2T(r, a) \
    asm volatile("ldmatrix.sync.aligned.m8n8.x2.trans.shared.b16 {%0,%1}, [%2];" \
        : "=r"((r)[0]), "=r"((r)[1]) : "r"(a))
#define MMA16816F(d, a, bb) \
    asm volatile("mma.sync.aligned.m16n8k16.row.col.f32.f16.f16.f32 " \
        "{%0,%1,%2,%3}, {%4,%5,%6,%7}, {%8,%9}, {%0,%1,%2,%3};" \
        : "+f"((d)[0]), "+f"((d)[1]), "+f"((d)[2]), "+f"((d)[3]) \
        : "r"((a)[0]), "r"((a)[1]), "r"((a)[2]), "r"((a)[3]), "r"((bb)[0]), "r"((bb)[1]))

// fold one accumulator with a compile-time-constant coefficient
__device__ __forceinline__ void fold1(float& y, float coef, float v) {
    if (coef == 1.0f)       y += v;
    else if (coef == -1.0f) y -= v;
    else if (coef != 0.0f)  y = fmaf(coef, v, y);
}

// ---------------- U = G g G^T ----------------
__global__ void wu_kernel(const float* __restrict__ w)
{
    const int co = blockIdx.x;
    const int ci = threadIdx.x;
    const float* g = w + (co * CI + ci) * 9;
    float q[3][3];
#pragma unroll
    for (int r = 0; r < 3; ++r)
#pragma unroll
        for (int c = 0; c < 3; ++c) q[r][c] = g[r * 3 + c];
    float t[4][3];
#pragma unroll
    for (int c = 0; c < 3; ++c) {
        t[0][c] = q[0][c];
        t[1][c] = 0.5f * (q[0][c] + q[1][c] + q[2][c]);
        t[2][c] = 0.5f * (q[0][c] - q[1][c] + q[2][c]);
        t[3][c] = q[2][c];
    }
#pragma unroll
    for (int r = 0; r < 4; ++r) {
        float u0 = t[r][0];
        float u1 = 0.5f * (t[r][0] + t[r][1] + t[r][2]);
        float u2 = 0.5f * (t[r][0] - t[r][1] + t[r][2]);
        float u3 = t[r][2];
        g_U[((r * 4 + 0) * CO + co) * CI + ci] = __float2half(u0);
        g_U[((r * 4 + 1) * CO + co) * CI + ci] = __float2half(u1);
        g_U[((r * 4 + 2) * CO + co) * CI + ci] = __float2half(u2);
        g_U[((r * 4 + 3) * CO + co) * CI + ci] = __float2half(u3);
    }
}

// ---------------- fused: transform + GEMM + output transform + pool ----------------
__global__ void __launch_bounds__(512, 1)
wino_fused(const float* __restrict__ x, const float* __restrict__ bias)
{
    extern __shared__ char smem[];
    const uint32_t sb = smem_u32(smem);
    const int tid  = threadIdx.x;
    const int wid  = tid >> 5;
    const int lane = tid & 31;
    const int mg = wid & 3;        // co quarter (32 rows)
    const int ng = wid >> 2;       // 16-tile group (0..3)

    const int th = blockIdx.x;     // 0..62
    const int b  = blockIdx.y;

    const uint64_t gU = to_global(g_U);

    // ---- A-stage prefetch (issued BEFORE phase 1 so U streams in under it) ----
    auto loadA_stage = [&](int s, int buf) {
        const uint32_t aOff = sb + A_OFF + (uint32_t)buf * A_STG;
#pragma unroll
        for (int k = 0; k < 2; ++k) {
            const int c = 2 * s + k;
#pragma unroll
            for (int it = 0; it < 2; ++it) {
                int idx = tid + it * 512;       // 0..1023
                int co = idx >> 3, q = idx & 7;
                CP16(aOff + k * A_CB + co * 144 + q * 16,
                     gU + ((uint64_t)c << 14) + co * 128 + q * 16);
            }
        }
    };

    loadA_stage(0, 0); CP_COMMIT();
    loadA_stage(1, 1); CP_COMMIT();

    // ---- phase 1: direct-LDG input transform, no staging, no barriers ----
    const int ci_l = tid >> 5;     // 0..15
    const int tp   = tid & 31;     // tile pair
    const int tw0  = tp * 2;
    const bool v1  = (tw0 + 1) < NT1;

    const float* xb = x + (size_t)b * CI * HW_ + (size_t)th * 2 * WW + 4 * tp;
    const float* xlast = x + (size_t)B_ * CI * HW_ - 2;   // clamp for tail overread

#pragma unroll
    for (int g = 0; g < 4; ++g) {
        const int ci = g * 16 + ci_l;
        const float* base = xb + (size_t)ci * HW_;
        float dd[4][6];
#pragma unroll
        for (int r = 0; r < 4; ++r) {
            const float* row = base + r * WW;   // 16B-aligned
            float4 a01 = *(const float4*)(row);
            const float* p2 = row + 4;
            if (p2 > xlast) p2 = xlast;         // only feeds masked V1
            float2 a2 = *(const float2*)(p2);
            dd[r][0] = a01.x; dd[r][1] = a01.y; dd[r][2] = a01.z;
            dd[r][3] = a01.w; dd[r][4] = a2.x;  dd[r][5] = a2.y;
        }
        float V0[16], V1[16];
#pragma unroll
        for (int tile = 0; tile < 2; ++tile) {
            const int o = tile * 2;
            float E[4][4];
#pragma unroll
            for (int r = 0; r < 4; ++r) {
                E[r][0] = dd[r][o + 0] - dd[r][o + 2];
                E[r][1] = dd[r][o + 1] + dd[r][o + 2];
                E[r][2] = dd[r][o + 2] - dd[r][o + 1];
                E[r][3] = dd[r][o + 1] - dd[r][o + 3];
            }
            float* V = tile ? V1 : V0;
#pragma unroll
            for (int j = 0; j < 4; ++j) {
                V[0 * 4 + j] = E[0][j] - E[2][j];
                V[1 * 4 + j] = E[1][j] + E[2][j];
                V[2 * 4 + j] = E[2][j] - E[1][j];
                V[3 * 4 + j] = E[1][j] - E[3][j];
            }
        }
        char* vdst = smem + ci * 144 + tp * 4;
#pragma unroll
        for (int c = 0; c < 16; ++c) {
            __half2 pk = __floats2half2_rn(V0[c], v1 ? V1[c] : 0.0f);
            *(uint32_t*)(vdst + c * V_CB) = reinterpret_cast<uint32_t&>(pk);
        }
    }
    // V visibility handled by the stage-0 __syncthreads below.

    // ---- phase 2: 8 stages x 2 comps, FULLY UNROLLED (fold coeffs fold away) ----
    float y[2][2][4][4];   // [mf][nf][e][q]
#pragma unroll
    for (int a = 0; a < 2; ++a)
#pragma unroll
        for (int n = 0; n < 2; ++n)
#pragma unroll
            for (int e = 0; e < 4; ++e)
#pragma unroll
                for (int q = 0; q < 4; ++q) y[a][n][e][q] = 0.0f;

    const uint32_t aBase = sb + A_OFF + (mg * 32 + (lane & 15)) * 144 + (lane >> 4) * 16;
    const uint32_t bBase = sb + (lane & 15) * 144 + ng * 32;

#pragma unroll
    for (int s = 0; s < 8; ++s) {
        if (s < 7) { CP_WAIT1(); } else { CP_WAIT0(); }
        __syncthreads();
        const uint32_t stA = (uint32_t)(s & 1) * A_STG;

#pragma unroll
        for (int k = 0; k < 2; ++k) {
            const int c = 2 * s + k;
            const uint32_t curA = stA + (uint32_t)k * A_CB;
            const uint32_t curB = (uint32_t)c * V_CB;

            float m[2][2][4];
#pragma unroll
            for (int mf = 0; mf < 2; ++mf)
#pragma unroll
                for (int nf = 0; nf < 2; ++nf)
#pragma unroll
                    for (int e = 0; e < 4; ++e) m[mf][nf][e] = 0.0f;

#pragma unroll
            for (int s4 = 0; s4 < 4; ++s4) {
                uint32_t afr[2][4], bfr[2][2];
#pragma unroll
                for (int mf = 0; mf < 2; ++mf)
                    LDSM_X4(afr[mf], aBase + curA + mf * 16 * 144 + s4 * 32);
#pragma unroll
                for (int nf = 0; nf < 2; ++nf)
                    LDSM_X2T(bfr[nf], bBase + curB + s4 * 16 * 144 + nf * 16);
#pragma unroll
                for (int mf = 0; mf < 2; ++mf)
#pragma unroll
                    for (int nf = 0; nf < 2; ++nf)
                        MMA16816F(m[mf][nf], afr[mf], bfr[nf]);
            }

            // fold (AT0={1,1,1,0}, AT1={0,1,-1,-1}); c is compile-time here
            const int cr = c >> 2, cc = c & 3;
            const float a0r = (cr < 3) ? 1.0f : 0.0f;
            const float a1r = (cr == 0) ? 0.0f : ((cr == 1) ? 1.0f : -1.0f);
            const float a0c = (cc < 3) ? 1.0f : 0.0f;
            const float a1c = (cc == 0) ? 0.0f : ((cc == 1) ? 1.0f : -1.0f);
            const float cq0 = a0r * a0c, cq1 = a0r * a1c;
            const float cq2 = a1r * a0c, cq3 = a1r * a1c;
#pragma unroll
            for (int mf = 0; mf < 2; ++mf)
#pragma unroll
                for (int nf = 0; nf < 2; ++nf)
#pragma unroll
                    for (int e = 0; e < 4; ++e) {
                        const float v = m[mf][nf][e];
                        fold1(y[mf][nf][e][0], cq0, v);
                        fold1(y[mf][nf][e][1], cq1, v);
                        fold1(y[mf][nf][e][2], cq2, v);
                        fold1(y[mf][nf][e][3], cq3, v);
                    }
        }
        __syncthreads();
        if (s + 2 < 8) { loadA_stage(s + 2, s & 1); CP_COMMIT(); }
    }

    // ---- epilogue: bias + gelu + pool ----
    float* red = (float*)smem;     // aliases V (dead)
#pragma unroll
    for (int mf = 0; mf < 2; ++mf) {
#pragma unroll
        for (int hh = 0; hh < 2; ++hh) {
            const int co = mg * 32 + mf * 16 + hh * 8 + (lane >> 2);
            const float bv = __ldg(bias + co);
            float s = 0.0f;
#pragma unroll
            for (int nf = 0; nf < 2; ++nf) {
#pragma unroll
                for (int e = 0; e < 2; ++e) {
                    const int tw = ng * 16 + nf * 8 + (lane & 3) * 2 + e;
                    if (tw < NT1) {
#pragma unroll
                        for (int q = 0; q < 4; ++q)
                            s += gelu_t(y[mf][nf][hh * 2 + e][q] + bv);
                    }
                }
            }
            s += __shfl_xor_sync(0xFFFFFFFFu, s, 1);
            s += __shfl_xor_sync(0xFFFFFFFFu, s, 2);
            if ((lane & 3) == 0) red[ng * CO + co] = s;
        }
    }
    __syncthreads();
    if (tid < CO) {
        float t = red[tid] + red[CO + tid] + red[2 * CO + tid] + red[3 * CO + tid];
        g_partial[(b * NT1 + th) * CO + tid] = t;
    }
}

// ---------------- final reduction ----------------
__global__ void reduce_kernel(float* __restrict__ out)
{
    __shared__ float sred[512];
    const int b   = blockIdx.x;
    const int co  = threadIdx.x & 127;
    const int seg = threadIdx.x >> 7;
    const int r0 = seg * 16;
    const int r1 = (seg == 3) ? NT1 : (r0 + 16);
    float s = 0.0f;
    for (int r = r0; r < r1; ++r)
        s += g_partial[(b * NT1 + r) * CO + co];
    sred[threadIdx.x] = s;
    __syncthreads();
    if (threadIdx.x < 128) {
        float r = sred[threadIdx.x] + sred[threadIdx.x + 128]
                + sred[threadIdx.x + 256] + sred[threadIdx.x + 384];
        out[b * CO + threadIdx.x] = r * (1.0f / (float)(OH * OW));
    }
}

extern "C" void kernel_launch(void* const* d_in, const int* in_sizes, int n_in,
                              void* d_out, int out_size)
{
    const float* x      = (const float*)d_in[0];
    const float* weight = (const float*)d_in[1];
    const float* bias   = (const float*)d_in[2];
    float* out = (float*)d_out;

    cudaFuncSetAttribute(wino_fused,
                         cudaFuncAttributeMaxDynamicSharedMemorySize, SMEM_DYN);

    wu_kernel<<<CO, CI>>>(weight);
    wino_fused<<<dim3(NT1, B_), 512, SMEM_DYN>>>(x, bias);
    reduce_kernel<<<B_, 512>>>(out);
}

// round 16
// speedup vs baseline: 1.7950x; 1.0450x over previous
#include <cuda_runtime.h>
#include <cuda_fp16.h>
#include <math.h>
#include <stdint.h>

// ---------------- problem constants ----------------
#define B_   32
#define CI   64
#define HH   128
#define WW   128
#define HW_  16384
#define OH   126
#define OW   126
#define CO   128
#define NT1  63
#define NCOMP 16

// ---------------- device scratch ----------------
__device__ __half g_U[NCOMP * CO * CI];     // 256 KB [c][co][ci]
__device__ float  g_partial[B_ * NT1 * CO]; // [b][th][co]

// ---------------- smem layout (bytes) ----------------
// V: 16 comps x 64 ci x 128B (XOR-swizzled chunks)
#define V_CB     8192
#define A_OFF    (16 * V_CB)            // 131072
// A: 128 co x 128B per comp (XOR-swizzled); stage = 2 comps; 3 buffers
#define A_CB     16384
#define A_STG    (2 * A_CB)             // 32768
#define SMEM_DYN (A_OFF + 3 * A_STG)    // 229376 (224 KB)

// ---------------- helpers ----------------
__device__ __forceinline__ uint32_t smem_u32(const void* p) {
    uint32_t a;
    asm("{ .reg .u64 t; cvta.to.shared.u64 t, %1; cvt.u32.u64 %0, t; }" : "=r"(a) : "l"(p));
    return a;
}
__device__ __forceinline__ uint64_t to_global(const void* p) {
    uint64_t g;
    asm("cvta.to.global.u64 %0, %1;" : "=l"(g) : "l"(p));
    return g;
}
__device__ __forceinline__ float gelu_t(float v) {
    float u = 0.7978845608028654f * fmaf(0.044715f * v, v * v, v);
    float t;
    asm("tanh.approx.f32 %0, %1;" : "=f"(t) : "f"(u));
    return 0.5f * v * (1.0f + t);
}

#define CP16(dst, src) asm volatile("cp.async.ca.shared.global [%0], [%1], 16;" :: "r"(dst), "l"(src))
#define CP_COMMIT()    asm volatile("cp.async.commit_group;" ::: "memory")
#define CP_WAIT1()     asm volatile("cp.async.wait_group 1;" ::: "memory")
#define CP_WAIT0()     asm volatile("cp.async.wait_group 0;" ::: "memory")

#define LDSM_X4(r, a) \
    asm volatile("ldmatrix.sync.aligned.m8n8.x4.shared.b16 {%0,%1,%2,%3}, [%4];" \
        : "=r"((r)[0]), "=r"((r)[1]), "=r"((r)[2]), "=r"((r)[3]) : "r"(a))
#define LDSM_X2T(r, a) \
    asm volatile("ldmatrix.sync.aligned.m8n8.x2.trans.shared.b16 {%0,%1}, [%2];" \
        : "=r"((r)[0]), "=r"((r)[1]) : "r"(a))
#define MMA16816F(d, a, bb) \
    asm volatile("mma.sync.aligned.m16n8k16.row.col.f32.f16.f16.f32 " \
        "{%0,%1,%2,%3}, {%4,%5,%6,%7}, {%8,%9}, {%0,%1,%2,%3};" \
        : "+f"((d)[0]), "+f"((d)[1]), "+f"((d)[2]), "+f"((d)[3]) \
        : "r"((a)[0]), "r"((a)[1]), "r"((a)[2]), "r"((a)[3]), "r"((bb)[0]), "r"((bb)[1]))

// fold one accumulator with a compile-time-constant coefficient
__device__ __forceinline__ void fold1(float& y, float coef, float v) {
    if (coef == 1.0f)       y += v;
    else if (coef == -1.0f) y -= v;
    else if (coef != 0.0f)  y = fmaf(coef, v, y);
}

// ---------------- U = G g G^T ----------------
__global__ void wu_kernel(const float* __restrict__ w)
{
    const int co = blockIdx.x;
    const int ci = threadIdx.x;
    const float* g = w + (co * CI + ci) * 9;
    float q[3][3];
#pragma unroll
    for (int r = 0; r < 3; ++r)
#pragma unroll
        for (int c = 0; c < 3; ++c) q[r][c] = g[r * 3 + c];
    float t[4][3];
#pragma unroll
    for (int c = 0; c < 3; ++c) {
        t[0][c] = q[0][c];
        t[1][c] = 0.5f * (q[0][c] + q[1][c] + q[2][c]);
        t[2][c] = 0.5f * (q[0][c] - q[1][c] + q[2][c]);
        t[3][c] = q[2][c];
    }
#pragma unroll
    for (int r = 0; r < 4; ++r) {
        float u0 = t[r][0];
        float u1 = 0.5f * (t[r][0] + t[r][1] + t[r][2]);
        float u2 = 0.5f * (t[r][0] - t[r][1] + t[r][2]);
        float u3 = t[r][2];
        g_U[((r * 4 + 0) * CO + co) * CI + ci] = __float2half(u0);
        g_U[((r * 4 + 1) * CO + co) * CI + ci] = __float2half(u1);
        g_U[((r * 4 + 2) * CO + co) * CI + ci] = __float2half(u2);
        g_U[((r * 4 + 3) * CO + co) * CI + ci] = __float2half(u3);
    }
}

// ---------------- fused: transform + GEMM + output transform + pool ----------------
__global__ void __launch_bounds__(512, 1)
wino_fused(const float* __restrict__ x, const float* __restrict__ bias)
{
    extern __shared__ char smem[];
    const uint32_t sb = smem_u32(smem);
    const int tid  = threadIdx.x;
    const int wid  = tid >> 5;
    const int lane = tid & 31;
    const int mg = wid & 3;        // co quarter (32 rows)
    const int ng = wid >> 2;       // 16-tile group (0..3)

    const int th = blockIdx.x;     // 0..62
    const int b  = blockIdx.y;

    const uint64_t gU = to_global(g_U);

    // ---- A-stage prefetch (XOR-swizzled 128B rows) ----
    auto loadA_stage = [&](int s, int buf) {
        const uint32_t aOff = sb + A_OFF + (uint32_t)buf * A_STG;
#pragma unroll
        for (int k = 0; k < 2; ++k) {
            const int c = 2 * s + k;
#pragma unroll
            for (int it = 0; it < 2; ++it) {
                int idx = tid + it * 512;       // 0..1023
                int co = idx >> 3, q = idx & 7;
                CP16(aOff + k * A_CB + co * 128 + ((q ^ (co & 7)) << 4),
                     gU + ((uint64_t)c << 14) + co * 128 + q * 16);
            }
        }
    };

    loadA_stage(0, 0); CP_COMMIT();
    loadA_stage(1, 1); CP_COMMIT();

    // ---- phase 1: direct-LDG input transform, no barriers ----
    const int ci_l = tid >> 5;     // 0..15
    const int tp   = tid & 31;     // tile pair
    const int tw0  = tp * 2;
    const bool v1  = (tw0 + 1) < NT1;

    const float* xb = x + (size_t)b * CI * HW_ + (size_t)th * 2 * WW + 4 * tp;
    const float* xlast = x + (size_t)B_ * CI * HW_ - 2;   // clamp for tail overread

#pragma unroll
    for (int g = 0; g < 4; ++g) {
        const int ci = g * 16 + ci_l;
        const float* base = xb + (size_t)ci * HW_;
        float dd[4][6];
#pragma unroll
        for (int r = 0; r < 4; ++r) {
            const float* row = base + r * WW;   // 16B-aligned
            float4 a01 = *(const float4*)(row);
            const float* p2 = row + 4;
            if (p2 > xlast) p2 = xlast;         // only feeds masked V1
            float2 a2 = *(const float2*)(p2);
            dd[r][0] = a01.x; dd[r][1] = a01.y; dd[r][2] = a01.z;
            dd[r][3] = a01.w; dd[r][4] = a2.x;  dd[r][5] = a2.y;
        }
        float V0[16], V1[16];
#pragma unroll
        for (int tile = 0; tile < 2; ++tile) {
            const int o = tile * 2;
            float E[4][4];
#pragma unroll
            for (int r = 0; r < 4; ++r) {
                E[r][0] = dd[r][o + 0] - dd[r][o + 2];
                E[r][1] = dd[r][o + 1] + dd[r][o + 2];
                E[r][2] = dd[r][o + 2] - dd[r][o + 1];
                E[r][3] = dd[r][o + 1] - dd[r][o + 3];
            }
            float* V = tile ? V1 : V0;
#pragma unroll
            for (int j = 0; j < 4; ++j) {
                V[0 * 4 + j] = E[0][j] - E[2][j];
                V[1 * 4 + j] = E[1][j] + E[2][j];
                V[2 * 4 + j] = E[2][j] - E[1][j];
                V[3 * 4 + j] = E[1][j] - E[3][j];
            }
        }
        // swizzled V store: row ci (128B), chunk tp>>2 XOR (ci&7), word tp&3
        char* vdst = smem + ci * 128 + (((tp >> 2) ^ (ci & 7)) << 4) + (tp & 3) * 4;
#pragma unroll
        for (int c = 0; c < 16; ++c) {
            __half2 pk = __floats2half2_rn(V0[c], v1 ? V1[c] : 0.0f);
            *(uint32_t*)(vdst + c * V_CB) = reinterpret_cast<uint32_t&>(pk);
        }
    }
    // V visibility handled by the stage-0 __syncthreads below.

    // ---- phase 2: 8 stages x 2 comps, 3-buffer A, ONE barrier per stage ----
    float y[2][2][4][4];   // [mf][nf][e][q]
#pragma unroll
    for (int a = 0; a < 2; ++a)
#pragma unroll
        for (int n = 0; n < 2; ++n)
#pragma unroll
            for (int e = 0; e < 4; ++e)
#pragma unroll
                for (int q = 0; q < 4; ++q) y[a][n][e][q] = 0.0f;

    const int laneRow = mg * 32 + (lane & 15);
    const int lane7   = lane & 7;
    const int laneChk = lane >> 4;
    const int bRow    = lane & 15;

#pragma unroll
    for (int s = 0; s < 8; ++s) {
        if (s < 7) { CP_WAIT1(); } else { CP_WAIT0(); }
        __syncthreads();
        // prefetch s+2 into the buffer stage s-1 used (safe: sync above
        // guarantees all warps finished stage s-1 reads)
        if (s + 2 < 8) { loadA_stage(s + 2, (s + 2) % 3); CP_COMMIT(); }

        const uint32_t stA = sb + A_OFF + (uint32_t)(s % 3) * A_STG;

#pragma unroll
        for (int k = 0; k < 2; ++k) {
            const int c = 2 * s + k;
            const uint32_t curA = stA + (uint32_t)k * A_CB;
            const uint32_t curB = sb + (uint32_t)c * V_CB;

            float m[2][2][4];
#pragma unroll
            for (int mf = 0; mf < 2; ++mf)
#pragma unroll
                for (int nf = 0; nf < 2; ++nf)
#pragma unroll
                    for (int e = 0; e < 4; ++e) m[mf][nf][e] = 0.0f;

#pragma unroll
            for (int s4 = 0; s4 < 4; ++s4) {
                uint32_t afr[2][4], bfr[2][2];
                const int chunk = laneChk + s4 * 2;
                const uint32_t swA = (uint32_t)((chunk ^ lane7) << 4);
#pragma unroll
                for (int mf = 0; mf < 2; ++mf)
                    LDSM_X4(afr[mf], curA + (laneRow + mf * 16) * 128 + swA);
#pragma unroll
                for (int nf = 0; nf < 2; ++nf) {
                    const uint32_t swB = (uint32_t)(((ng * 2 + nf) ^ lane7) << 4);
                    LDSM_X2T(bfr[nf], curB + (s4 * 16 + bRow) * 128 + swB);
                }
#pragma unroll
                for (int mf = 0; mf < 2; ++mf)
#pragma unroll
                    for (int nf = 0; nf < 2; ++nf)
                        MMA16816F(m[mf][nf], afr[mf], bfr[nf]);
            }

            // fold (AT0={1,1,1,0}, AT1={0,1,-1,-1}); c is compile-time here
            const int cr = c >> 2, cc = c & 3;
            const float a0r = (cr < 3) ? 1.0f : 0.0f;
            const float a1r = (cr == 0) ? 0.0f : ((cr == 1) ? 1.0f : -1.0f);
            const float a0c = (cc < 3) ? 1.0f : 0.0f;
            const float a1c = (cc == 0) ? 0.0f : ((cc == 1) ? 1.0f : -1.0f);
            const float cq0 = a0r * a0c, cq1 = a0r * a1c;
            const float cq2 = a1r * a0c, cq3 = a1r * a1c;
#pragma unroll
            for (int mf = 0; mf < 2; ++mf)
#pragma unroll
                for (int nf = 0; nf < 2; ++nf)
#pragma unroll
                    for (int e = 0; e < 4; ++e) {
                        const float v = m[mf][nf][e];
                        fold1(y[mf][nf][e][0], cq0, v);
                        fold1(y[mf][nf][e][1], cq1, v);
                        fold1(y[mf][nf][e][2], cq2, v);
                        fold1(y[mf][nf][e][3], cq3, v);
                    }
        }
    }

    // ---- epilogue: bias + gelu + pool ----
    float* red = (float*)smem;     // aliases V comp 0 (long dead)
#pragma unroll
    for (int mf = 0; mf < 2; ++mf) {
#pragma unroll
        for (int hh = 0; hh < 2; ++hh) {
            const int co = mg * 32 + mf * 16 + hh * 8 + (lane >> 2);
            const float bv = __ldg(bias + co);
            float s = 0.0f;
#pragma unroll
            for (int nf = 0; nf < 2; ++nf) {
#pragma unroll
                for (int e = 0; e < 2; ++e) {
                    const int tw = ng * 16 + nf * 8 + (lane & 3) * 2 + e;
                    if (tw < NT1) {
#pragma unroll
                        for (int q = 0; q < 4; ++q)
                            s += gelu_t(y[mf][nf][hh * 2 + e][q] + bv);
                    }
                }
            }
            s += __shfl_xor_sync(0xFFFFFFFFu, s, 1);
            s += __shfl_xor_sync(0xFFFFFFFFu, s, 2);
            if ((lane & 3) == 0) red[ng * CO + co] = s;
        }
    }
    __syncthreads();
    if (tid < CO) {
        float t = red[tid] + red[CO + tid] + red[2 * CO + tid] + red[3 * CO + tid];
        g_partial[(b * NT1 + th) * CO + tid] = t;
    }
}

// ---------------- final reduction ----------------
__global__ void reduce_kernel(float* __restrict__ out)
{
    __shared__ float sred[512];
    const int b   = blockIdx.x;
    const int co  = threadIdx.x & 127;
    const int seg = threadIdx.x >> 7;
    const int r0 = seg * 16;
    const int r1 = (seg == 3) ? NT1 : (r0 + 16);
    float s = 0.0f;
    for (int r = r0; r < r1; ++r)
        s += g_partial[(b * NT1 + r) * CO + co];
    sred[threadIdx.x] = s;
    __syncthreads();
    if (threadIdx.x < 128) {
        float r = sred[threadIdx.x] + sred[threadIdx.x + 128]
                + sred[threadIdx.x + 256] + sred[threadIdx.x + 384];
        out[b * CO + threadIdx.x] = r * (1.0f / (float)(OH * OW));
    }
}

extern "C" void kernel_launch(void* const* d_in, const int* in_sizes, int n_in,
                              void* d_out, int out_size)
{
    const float* x      = (const float*)d_in[0];
    const float* weight = (const float*)d_in[1];
    const float* bias   = (const float*)d_in[2];
    float* out = (float*)d_out;

    cudaFuncSetAttribute(wino_fused,
                         cudaFuncAttributeMaxDynamicSharedMemorySize, SMEM_DYN);

    wu_kernel<<<CO, CI>>>(weight);
    wino_fused<<<dim3(NT1, B_), 512, SMEM_DYN>>>(x, bias);
    reduce_kernel<<<B_, 512>>>(out);
}